// round 5
// baseline (speedup 1.0000x reference)
#include <cuda_runtime.h>
#include <cuda_bf16.h>
#include <cstdint>

#define BB 4
#define KK 64
#define LL 128
#define DD 768
#define NBK (BB*KK)          // 256
#define NROWS (NBK*LL)       // 32768 per side
#define TROWS (2*NROWS)      // 65536
#define KV 1536              // packed hi|lo row length (bf16)

// ---------------- scratch ----------------
__device__ float g_ctx_n[(size_t)NROWS * DD];
__device__ float g_ent_n[(size_t)NROWS * DD];
__device__ __nv_bfloat16 g_xb[(size_t)TROWS * KV];   // [row][hi 768 | lo 768]
__device__ __nv_bfloat16 g_w1b[(size_t)DD * KV];     // [n][hi 768 | lo 768]
__device__ float g_f[TROWS];
__device__ int   g_amax[NROWS];

// ---------------- helpers ----------------
__device__ __forceinline__ uint32_t smem_u32(const void* p) {
    uint32_t a;
    asm("{ .reg .u64 t; cvta.to.shared.u64 t, %1; cvt.u32.u64 %0, t; }" : "=r"(a) : "l"(p));
    return a;
}
#define CP_ASYNC16(sa, ga) \
    asm volatile("{ .reg .u64 g; cvta.to.global.u64 g, %1; cp.async.cg.shared.global [%0], [g], 16; }" \
        :: "r"(sa), "l"(ga) : "memory")
#define CP_COMMIT() asm volatile("cp.async.commit_group;" ::: "memory")
#define CP_WAIT2()  asm volatile("cp.async.wait_group 2;" ::: "memory")
#define CP_WAIT1()  asm volatile("cp.async.wait_group 1;" ::: "memory")
#define CP_WAIT0()  asm volatile("cp.async.wait_group 0;" ::: "memory")

#define LDSM4(r0, r1, r2, r3, a) \
    asm volatile("ldmatrix.sync.aligned.m8n8.x4.shared.b16 {%0,%1,%2,%3}, [%4];" \
        : "=r"(r0), "=r"(r1), "=r"(r2), "=r"(r3) : "r"(a))

#define MMA16816(d, a0, a1, a2, a3, b0, b1) \
    asm volatile("mma.sync.aligned.m16n8k16.row.col.f32.bf16.bf16.f32 " \
        "{%0,%1,%2,%3},{%4,%5,%6,%7},{%8,%9},{%0,%1,%2,%3};" \
        : "+f"((d)[0]), "+f"((d)[1]), "+f"((d)[2]), "+f"((d)[3]) \
        : "r"(a0), "r"(a1), "r"(a2), "r"(a3), "r"(b0), "r"(b1))

// ---------- packed f32x2 (scores kernel) ----------
__device__ __forceinline__ unsigned long long pk2(float lo, float hi) {
    unsigned long long r;
    asm("mov.b64 %0, {%1,%2};" : "=l"(r) : "f"(lo), "f"(hi));
    return r;
}
__device__ __forceinline__ void upk2(unsigned long long v, float& lo, float& hi) {
    asm("mov.b64 {%0,%1}, %2;" : "=f"(lo), "=f"(hi) : "l"(v));
}
__device__ __forceinline__ void ffma2(unsigned long long& d,
                                      unsigned long long a, unsigned long long b) {
    asm("fma.rn.f32x2 %0, %1, %2, %0;" : "+l"(d) : "l"(a), "l"(b));
}

// ---------------------------------------------------------------
// K0: w1 -> transposed bf16 hi/lo
// ---------------------------------------------------------------
__global__ void __launch_bounds__(256) k_prep_w1(const float* __restrict__ w1) {
    int n = blockIdx.x;
    for (int k = threadIdx.x; k < DD; k += 256) {
        float v = w1[(size_t)k * DD + n];
        __nv_bfloat16 h = __float2bfloat16(v);
        g_w1b[(size_t)n * KV + k] = h;
        g_w1b[(size_t)n * KV + DD + k] = __float2bfloat16(v - __bfloat162float(h));
    }
}

// ---------------------------------------------------------------
// K1: normalize rows -> fp32 (scores) + packed bf16 hi|lo (MLP)
// ---------------------------------------------------------------
__global__ void __launch_bounds__(192) k_normalize(const float* __restrict__ ctxt) {
    __shared__ float red[6];
    int r = blockIdx.x;
    int tid = threadIdx.x;
    const float4* src = (const float4*)(ctxt + (size_t)r * DD);
    float4 v = src[tid];
    float ss = v.x*v.x + v.y*v.y + v.z*v.z + v.w*v.w;
    #pragma unroll
    for (int o = 16; o; o >>= 1) ss += __shfl_xor_sync(0xffffffffu, ss, o);
    if ((tid & 31) == 0) red[tid >> 5] = ss;
    __syncthreads();
    float tot = red[0] + red[1] + red[2] + red[3] + red[4] + red[5];
    float inv = 1.0f / sqrtf(tot);
    int l  = r % LL;
    int s  = (r / LL) & 1;
    int bk = r / (2 * LL);
    size_t row32 = (size_t)bk * LL + l;
    float4 o = make_float4(v.x*inv, v.y*inv, v.z*inv, v.w*inv);
    ((float4*)((s == 0 ? g_ctx_n : g_ent_n) + row32 * DD))[tid] = o;
    size_t urow = (size_t)s * NROWS + row32;
    __nv_bfloat16 h0 = __float2bfloat16(o.x), h1 = __float2bfloat16(o.y);
    __nv_bfloat16 h2 = __float2bfloat16(o.z), h3 = __float2bfloat16(o.w);
    __nv_bfloat162* ph = (__nv_bfloat162*)(g_xb + urow * KV) + tid * 2;
    __nv_bfloat162* pl = (__nv_bfloat162*)(g_xb + urow * KV + DD) + tid * 2;
    ph[0] = __nv_bfloat162(h0, h1);
    ph[1] = __nv_bfloat162(h2, h3);
    pl[0] = __nv_bfloat162(__float2bfloat16(o.x - __bfloat162float(h0)),
                           __float2bfloat16(o.y - __bfloat162float(h1)));
    pl[1] = __nv_bfloat162(__float2bfloat16(o.z - __bfloat162float(h2)),
                           __float2bfloat16(o.w - __bfloat162float(h3)));
}

// ---------------------------------------------------------------
// K2: fp32 cosine scores + argmax (exact; argmax is tie-sensitive)
// ---------------------------------------------------------------
__global__ void __launch_bounds__(256) k_scores() {
    __shared__ float As[16 * 128];
    __shared__ float Bs[16 * 128];
    __shared__ float sval[128 * 17];
    __shared__ int   sidx[128 * 17];

    int bk = blockIdx.x;
    const float* ctxp = g_ctx_n + (size_t)bk * LL * DD;
    const float* entp = g_ent_n + (size_t)bk * LL * DD;
    int tid = threadIdx.x;
    int tm = tid & 15, tn = tid >> 4;
    int m0 = tm * 8, n0 = tn * 8;

    unsigned long long c2[8][4];
    #pragma unroll
    for (int i = 0; i < 8; i++)
        #pragma unroll
        for (int j = 0; j < 4; j++) c2[i][j] = 0ULL;

    int mrow = tid & 127;
    int hf = tid >> 7;

    for (int kt = 0; kt < 48; kt++) {
        __syncthreads();
        const float4* a4 = (const float4*)(ctxp + (size_t)mrow * DD + kt * 16);
        const float4* b4 = (const float4*)(entp + (size_t)mrow * DD + kt * 16);
        #pragma unroll
        for (int u = 0; u < 2; u++) {
            int kq = hf * 2 + u;
            float4 v = a4[kq];
            int k4 = kq * 4;
            As[(k4+0)*128+mrow] = v.x; As[(k4+1)*128+mrow] = v.y;
            As[(k4+2)*128+mrow] = v.z; As[(k4+3)*128+mrow] = v.w;
            v = b4[kq];
            Bs[(k4+0)*128+mrow] = v.x; Bs[(k4+1)*128+mrow] = v.y;
            Bs[(k4+2)*128+mrow] = v.z; Bs[(k4+3)*128+mrow] = v.w;
        }
        __syncthreads();
        #pragma unroll
        for (int kk = 0; kk < 16; kk++) {
            float4 aA = *(const float4*)(As + kk*128 + m0);
            float4 aB = *(const float4*)(As + kk*128 + m0 + 4);
            float4 bA = *(const float4*)(Bs + kk*128 + n0);
            float4 bB = *(const float4*)(Bs + kk*128 + n0 + 4);
            unsigned long long ap[8], bp[4];
            ap[0]=pk2(aA.x,aA.x); ap[1]=pk2(aA.y,aA.y); ap[2]=pk2(aA.z,aA.z); ap[3]=pk2(aA.w,aA.w);
            ap[4]=pk2(aB.x,aB.x); ap[5]=pk2(aB.y,aB.y); ap[6]=pk2(aB.z,aB.z); ap[7]=pk2(aB.w,aB.w);
            bp[0]=pk2(bA.x,bA.y); bp[1]=pk2(bA.z,bA.w); bp[2]=pk2(bB.x,bB.y); bp[3]=pk2(bB.z,bB.w);
            #pragma unroll
            for (int i = 0; i < 8; i++)
                #pragma unroll
                for (int j = 0; j < 4; j++) ffma2(c2[i][j], ap[i], bp[j]);
        }
    }

    #pragma unroll
    for (int i = 0; i < 8; i++) {
        float bv = -3.4e38f; int bi = 0;
        #pragma unroll
        for (int j = 0; j < 4; j++) {
            float lo, hi; upk2(c2[i][j], lo, hi);
            int n = n0 + 2 * j;
            if (lo > bv) { bv = lo; bi = n; }
            if (hi > bv) { bv = hi; bi = n + 1; }
        }
        sval[(m0 + i) * 17 + tn] = bv;
        sidx[(m0 + i) * 17 + tn] = bi;
    }
    __syncthreads();
    if (tid < 128) {
        float bv = sval[tid * 17]; int bi = sidx[tid * 17];
        #pragma unroll
        for (int t = 1; t < 16; t++) {
            float v = sval[tid * 17 + t];
            if (v > bv) { bv = v; bi = sidx[tid * 17 + t]; }
        }
        g_amax[bk * LL + tid] = bi;
    }
}

// ---------------------------------------------------------------
// K3 v3: MLP bf16 hi/lo 3-product mma.sync.
// CTA 128 rows x 64 cols (12 n-chunks), kchunk=32, hi|lo packed per
// 128B smem line, 4-stage cp.async ring, 2 CTAs/SM, product-major
// MMA order. 8 warps (2M x 4N), warp tile 64x16.
// ---------------------------------------------------------------
#define A_BYTES 16384                     // 128 lines x 128B (hi|lo)
#define B_BYTES 8192                      // 64 lines x 128B
#define STAGE_B (A_BYTES + B_BYTES)       // 24 KB
#define NSTAGE 4
#define NSTG 288                          // 12 nt x 24 kt
#define MLP_SMEM (NSTAGE * STAGE_B + 128 * 17 * 4)   // 98304 + 8704

__global__ void __launch_bounds__(256, 2) k_mlp_mma(const float* __restrict__ b1,
                                                    const float* __restrict__ w2,
                                                    const float* __restrict__ b2) {
    extern __shared__ char sm[];
    uint32_t sb = smem_u32(sm);
    float* red = (float*)(sm + NSTAGE * STAGE_B);

    int tid = threadIdx.x, lane = tid & 31, w = tid >> 5;
    int wm = w & 1, wn = w >> 1;
    size_t rowbase = (size_t)blockIdx.x * 128;

    // ---- producer mapping ----
    // A: row lr = tid>>1, half (tid&1): 0 = hi 64B, 1 = lo 64B
    int lr = tid >> 1;
    uint32_t a_cb = (uint32_t)(tid & 1) * 64;
    uint32_t a_swz = ((uint32_t)(lr & 7)) << 4;
    uint32_t a_srow = (uint32_t)lr * 128;
    const char* gA = (const char*)(g_xb + (rowbase + (size_t)lr) * KV)
                     + (size_t)(tid & 1) * 1536;
    // B: n-row nr = tid>>2, quarter q2 = tid&3 (q2<2 hi, q2>=2 lo)
    int nr = tid >> 2;
    int q2 = tid & 3;
    uint32_t b_cb = (uint32_t)q2 * 32;
    uint32_t b_swz = ((uint32_t)(nr & 7)) << 4;
    uint32_t b_srow = (uint32_t)nr * 128;
    uint32_t b_gcol = (uint32_t)(q2 & 1) * 32;
    size_t   b_glo  = (size_t)(q2 >> 1) * 1536;

    #define ISSUE(ntp, ktp, slot) do {                                            \
        uint32_t _st = sb + (uint32_t)(slot) * STAGE_B;                            \
        const char* _ga = gA + (ktp) * 64;                                         \
        uint32_t _sa = _st + a_srow;                                               \
        _Pragma("unroll")                                                          \
        for (int _q = 0; _q < 4; _q++)                                             \
            CP_ASYNC16(_sa + ((a_cb + _q * 16) ^ a_swz), _ga + _q * 16);           \
        const char* _gb = (const char*)g_w1b                                       \
            + ((size_t)((ntp) * 64 + nr)) * 3072 + b_glo + (ktp) * 64 + b_gcol;    \
        uint32_t _sbm = _st + A_BYTES + b_srow;                                    \
        CP_ASYNC16(_sbm + ((b_cb)      ^ b_swz), _gb);                             \
        CP_ASYNC16(_sbm + ((b_cb + 16) ^ b_swz), _gb + 16);                        \
        CP_COMMIT();                                                               \
    } while (0)

    // ---- consumer (ldmatrix) mapping ----
    int l15 = lane & 15;
    uint32_t sx = ((uint32_t)(lane & 7)) << 4;
    uint32_t l16 = (uint32_t)(lane >> 4) * 16;
    uint32_t aoff = (uint32_t)(wm * 64 + l15) * 128;
    uint32_t boff = (uint32_t)(wn * 16 + l15) * 128;

    float rs[4][2];
    #pragma unroll
    for (int i = 0; i < 4; i++) { rs[i][0] = 0.f; rs[i][1] = 0.f; }
    float acc[4][2][4];

    ISSUE(0, 0, 0);
    ISSUE(0, 1, 1);
    ISSUE(0, 2, 2);

    int nt = 0, kt = 0;           // consumer position
    int ntp = 0, ktp = 3;         // producer position (t+3)

    for (int t = 0; t < NSTG; t++) {
        if (t <= NSTG - 3)      CP_WAIT2();
        else if (t == NSTG - 2) CP_WAIT1();
        else                    CP_WAIT0();
        __syncthreads();
        if (t + 3 < NSTG) {
            ISSUE(ntp, ktp, (t + 3) & 3);
            if (++ktp == 24) { ktp = 0; ntp++; }
        }

        if (kt == 0) {
            #pragma unroll
            for (int i = 0; i < 4; i++)
                #pragma unroll
                for (int j = 0; j < 2; j++)
                    #pragma unroll
                    for (int q = 0; q < 4; q++) acc[i][j][q] = 0.f;
        }

        uint32_t stg = sb + (uint32_t)(t & 3) * STAGE_B;
        #pragma unroll
        for (int kk = 0; kk < 2; kk++) {
            uint32_t kbh = ((uint32_t)(kk * 32) + l16) ^ sx;
            uint32_t kbl = kbh ^ 64;
            uint32_t ah[4][4], al[4][4], th[4], tl[4];
            #pragma unroll
            for (int i = 0; i < 4; i++) {
                uint32_t ra = stg + aoff + (uint32_t)(i * 16 * 128);
                LDSM4(ah[i][0], ah[i][1], ah[i][2], ah[i][3], ra + kbh);
                LDSM4(al[i][0], al[i][1], al[i][2], al[i][3], ra + kbl);
            }
            uint32_t rb = stg + A_BYTES + boff;
            LDSM4(th[0], th[1], th[2], th[3], rb + kbh);
            LDSM4(tl[0], tl[1], tl[2], tl[3], rb + kbl);

            // product-major: 8 independent MMAs between accumulator reuses
            #pragma unroll
            for (int i = 0; i < 4; i++) {
                MMA16816(acc[i][0], ah[i][0], ah[i][1], ah[i][2], ah[i][3], th[0], th[2]);
                MMA16816(acc[i][1], ah[i][0], ah[i][1], ah[i][2], ah[i][3], th[1], th[3]);
            }
            #pragma unroll
            for (int i = 0; i < 4; i++) {
                MMA16816(acc[i][0], ah[i][0], ah[i][1], ah[i][2], ah[i][3], tl[0], tl[2]);
                MMA16816(acc[i][1], ah[i][0], ah[i][1], ah[i][2], ah[i][3], tl[1], tl[3]);
            }
            #pragma unroll
            for (int i = 0; i < 4; i++) {
                MMA16816(acc[i][0], al[i][0], al[i][1], al[i][2], al[i][3], th[0], th[2]);
                MMA16816(acc[i][1], al[i][0], al[i][1], al[i][2], al[i][3], th[1], th[3]);
            }
        }

        if (kt == 23) {
            #pragma unroll
            for (int j = 0; j < 2; j++) {
                int col = nt * 64 + wn * 16 + j * 8 + (lane & 3) * 2;
                float b1lo = __ldg(b1 + col), b1hi = __ldg(b1 + col + 1);
                float w2lo = __ldg(w2 + col), w2hi = __ldg(w2 + col + 1);
                #pragma unroll
                for (int i = 0; i < 4; i++) {
                    rs[i][0] += fmaxf(acc[i][j][0] + b1lo, 0.f) * w2lo
                              + fmaxf(acc[i][j][1] + b1hi, 0.f) * w2hi;
                    rs[i][1] += fmaxf(acc[i][j][2] + b1lo, 0.f) * w2lo
                              + fmaxf(acc[i][j][3] + b1hi, 0.f) * w2hi;
                }
            }
        }
        if (++kt == 24) { kt = 0; nt++; }
    }
    #undef ISSUE

    // cross-thread row reduction: 16 contributors per row
    __syncthreads();
    int rcol = wn * 4 + (lane & 3);
    #pragma unroll
    for (int i = 0; i < 4; i++) {
        int row = wm * 64 + i * 16 + (lane >> 2);
        red[row * 17 + rcol] = rs[i][0];
        red[(row + 8) * 17 + rcol] = rs[i][1];
    }
    __syncthreads();
    if (tid < 128) {
        float s = b2[0];
        #pragma unroll
        for (int t = 0; t < 16; t++) s += red[tid * 17 + t];
        g_f[rowbase + tid] = s;
    }
}

// ---------------------------------------------------------------
// K4: out = f(ctx_n) + f(ent_n[argmax])
// ---------------------------------------------------------------
__global__ void k_combine(float* __restrict__ out) {
    int i = blockIdx.x * 256 + threadIdx.x;
    int bk = i / LL;
    out[i] = g_f[i] + g_f[NROWS + bk * LL + g_amax[i]];
}

extern "C" void kernel_launch(void* const* d_in, const int* in_sizes, int n_in,
                              void* d_out, int out_size) {
    const float* context = (const float*)d_in[0];
    const float* w1 = (const float*)d_in[1];
    const float* b1 = (const float*)d_in[2];
    const float* w2 = (const float*)d_in[3];
    const float* b2 = (const float*)d_in[4];
    float* out = (float*)d_out;

    k_prep_w1<<<DD, 256>>>(w1);
    k_normalize<<<NBK * 2 * LL, 192>>>(context);
    k_scores<<<NBK, 256>>>();
    cudaFuncSetAttribute(k_mlp_mma, cudaFuncAttributeMaxDynamicSharedMemorySize, MLP_SMEM);
    k_mlp_mma<<<TROWS / 128, 256, MLP_SMEM>>>(b1, w2, b2);
    k_combine<<<NROWS / 256, 256>>>(out);
}

// round 6
// speedup vs baseline: 1.1353x; 1.1353x over previous
#include <cuda_runtime.h>
#include <cuda_bf16.h>
#include <cstdint>

#define BB 4
#define KK 64
#define LL 128
#define DD 768
#define NBK (BB*KK)          // 256
#define NROWS (NBK*LL)       // 32768 per side
#define TROWS (2*NROWS)      // 65536
#define KV 1536              // packed hi|lo row length (bf16)

// ---------------- scratch ----------------
__device__ float g_ctx_n[(size_t)NROWS * DD];
__device__ float g_ent_n[(size_t)NROWS * DD];
__device__ __nv_bfloat16 g_xb[(size_t)TROWS * KV];   // [row][hi 768 | lo 768]
__device__ __nv_bfloat16 g_w1b[(size_t)DD * KV];     // [n][hi 768 | lo 768]
__device__ float g_f[TROWS];
__device__ int   g_amax[NROWS];

// ---------------- helpers ----------------
__device__ __forceinline__ uint32_t smem_u32(const void* p) {
    uint32_t a;
    asm("{ .reg .u64 t; cvta.to.shared.u64 t, %1; cvt.u32.u64 %0, t; }" : "=r"(a) : "l"(p));
    return a;
}
#define CP_ASYNC16(sa, ga) \
    asm volatile("{ .reg .u64 g; cvta.to.global.u64 g, %1; cp.async.cg.shared.global [%0], [g], 16; }" \
        :: "r"(sa), "l"(ga) : "memory")
#define CP_COMMIT() asm volatile("cp.async.commit_group;" ::: "memory")
#define CP_WAIT1()  asm volatile("cp.async.wait_group 1;" ::: "memory")
#define CP_WAIT0()  asm volatile("cp.async.wait_group 0;" ::: "memory")

#define LDSM4(r, a) \
    asm volatile("ldmatrix.sync.aligned.m8n8.x4.shared.b16 {%0,%1,%2,%3}, [%4];" \
        : "=r"((r)[0]), "=r"((r)[1]), "=r"((r)[2]), "=r"((r)[3]) : "r"(a))

#define MMA16816(d, a, b0, b1) \
    asm volatile("mma.sync.aligned.m16n8k16.row.col.f32.bf16.bf16.f32 " \
        "{%0,%1,%2,%3},{%4,%5,%6,%7},{%8,%9},{%0,%1,%2,%3};" \
        : "+f"((d)[0]), "+f"((d)[1]), "+f"((d)[2]), "+f"((d)[3]) \
        : "r"((a)[0]), "r"((a)[1]), "r"((a)[2]), "r"((a)[3]), "r"(b0), "r"(b1))

// ---------- packed f32x2 (scores kernel) ----------
__device__ __forceinline__ unsigned long long pk2(float lo, float hi) {
    unsigned long long r;
    asm("mov.b64 %0, {%1,%2};" : "=l"(r) : "f"(lo), "f"(hi));
    return r;
}
__device__ __forceinline__ void upk2(unsigned long long v, float& lo, float& hi) {
    asm("mov.b64 {%0,%1}, %2;" : "=f"(lo), "=f"(hi) : "l"(v));
}
__device__ __forceinline__ void ffma2(unsigned long long& d,
                                      unsigned long long a, unsigned long long b) {
    asm("fma.rn.f32x2 %0, %1, %2, %0;" : "+l"(d) : "l"(a), "l"(b));
}

// ---------------------------------------------------------------
// K0: w1 -> transposed bf16 hi/lo
// ---------------------------------------------------------------
__global__ void __launch_bounds__(256) k_prep_w1(const float* __restrict__ w1) {
    int n = blockIdx.x;
    for (int k = threadIdx.x; k < DD; k += 256) {
        float v = w1[(size_t)k * DD + n];
        __nv_bfloat16 h = __float2bfloat16(v);
        g_w1b[(size_t)n * KV + k] = h;
        g_w1b[(size_t)n * KV + DD + k] = __float2bfloat16(v - __bfloat162float(h));
    }
}

// ---------------------------------------------------------------
// K1: normalize rows -> fp32 (scores) + packed bf16 hi|lo (MLP)
// ---------------------------------------------------------------
__global__ void __launch_bounds__(192) k_normalize(const float* __restrict__ ctxt) {
    __shared__ float red[6];
    int r = blockIdx.x;
    int tid = threadIdx.x;
    const float4* src = (const float4*)(ctxt + (size_t)r * DD);
    float4 v = src[tid];
    float ss = v.x*v.x + v.y*v.y + v.z*v.z + v.w*v.w;
    #pragma unroll
    for (int o = 16; o; o >>= 1) ss += __shfl_xor_sync(0xffffffffu, ss, o);
    if ((tid & 31) == 0) red[tid >> 5] = ss;
    __syncthreads();
    float tot = red[0] + red[1] + red[2] + red[3] + red[4] + red[5];
    float inv = 1.0f / sqrtf(tot);
    int l  = r % LL;
    int s  = (r / LL) & 1;
    int bk = r / (2 * LL);
    size_t row32 = (size_t)bk * LL + l;
    float4 o = make_float4(v.x*inv, v.y*inv, v.z*inv, v.w*inv);
    ((float4*)((s == 0 ? g_ctx_n : g_ent_n) + row32 * DD))[tid] = o;
    size_t urow = (size_t)s * NROWS + row32;
    __nv_bfloat16 h0 = __float2bfloat16(o.x), h1 = __float2bfloat16(o.y);
    __nv_bfloat16 h2 = __float2bfloat16(o.z), h3 = __float2bfloat16(o.w);
    __nv_bfloat162* ph = (__nv_bfloat162*)(g_xb + urow * KV) + tid * 2;
    __nv_bfloat162* pl = (__nv_bfloat162*)(g_xb + urow * KV + DD) + tid * 2;
    ph[0] = __nv_bfloat162(h0, h1);
    ph[1] = __nv_bfloat162(h2, h3);
    pl[0] = __nv_bfloat162(__float2bfloat16(o.x - __bfloat162float(h0)),
                           __float2bfloat16(o.y - __bfloat162float(h1)));
    pl[1] = __nv_bfloat162(__float2bfloat16(o.z - __bfloat162float(h2)),
                           __float2bfloat16(o.w - __bfloat162float(h3)));
}

// ---------------------------------------------------------------
// K2: fp32 cosine scores + argmax (exact; argmax is tie-sensitive)
// ---------------------------------------------------------------
__global__ void __launch_bounds__(256) k_scores() {
    __shared__ float As[16 * 128];
    __shared__ float Bs[16 * 128];
    __shared__ float sval[128 * 17];
    __shared__ int   sidx[128 * 17];

    int bk = blockIdx.x;
    const float* ctxp = g_ctx_n + (size_t)bk * LL * DD;
    const float* entp = g_ent_n + (size_t)bk * LL * DD;
    int tid = threadIdx.x;
    int tm = tid & 15, tn = tid >> 4;
    int m0 = tm * 8, n0 = tn * 8;

    unsigned long long c2[8][4];
    #pragma unroll
    for (int i = 0; i < 8; i++)
        #pragma unroll
        for (int j = 0; j < 4; j++) c2[i][j] = 0ULL;

    int mrow = tid & 127;
    int hf = tid >> 7;

    for (int kt = 0; kt < 48; kt++) {
        __syncthreads();
        const float4* a4 = (const float4*)(ctxp + (size_t)mrow * DD + kt * 16);
        const float4* b4 = (const float4*)(entp + (size_t)mrow * DD + kt * 16);
        #pragma unroll
        for (int u = 0; u < 2; u++) {
            int kq = hf * 2 + u;
            float4 v = a4[kq];
            int k4 = kq * 4;
            As[(k4+0)*128+mrow] = v.x; As[(k4+1)*128+mrow] = v.y;
            As[(k4+2)*128+mrow] = v.z; As[(k4+3)*128+mrow] = v.w;
            v = b4[kq];
            Bs[(k4+0)*128+mrow] = v.x; Bs[(k4+1)*128+mrow] = v.y;
            Bs[(k4+2)*128+mrow] = v.z; Bs[(k4+3)*128+mrow] = v.w;
        }
        __syncthreads();
        #pragma unroll
        for (int kk = 0; kk < 16; kk++) {
            float4 aA = *(const float4*)(As + kk*128 + m0);
            float4 aB = *(const float4*)(As + kk*128 + m0 + 4);
            float4 bA = *(const float4*)(Bs + kk*128 + n0);
            float4 bB = *(const float4*)(Bs + kk*128 + n0 + 4);
            unsigned long long ap[8], bp[4];
            ap[0]=pk2(aA.x,aA.x); ap[1]=pk2(aA.y,aA.y); ap[2]=pk2(aA.z,aA.z); ap[3]=pk2(aA.w,aA.w);
            ap[4]=pk2(aB.x,aB.x); ap[5]=pk2(aB.y,aB.y); ap[6]=pk2(aB.z,aB.z); ap[7]=pk2(aB.w,aB.w);
            bp[0]=pk2(bA.x,bA.y); bp[1]=pk2(bA.z,bA.w); bp[2]=pk2(bB.x,bB.y); bp[3]=pk2(bB.z,bB.w);
            #pragma unroll
            for (int i = 0; i < 8; i++)
                #pragma unroll
                for (int j = 0; j < 4; j++) ffma2(c2[i][j], ap[i], bp[j]);
        }
    }

    #pragma unroll
    for (int i = 0; i < 8; i++) {
        float bv = -3.4e38f; int bi = 0;
        #pragma unroll
        for (int j = 0; j < 4; j++) {
            float lo, hi; upk2(c2[i][j], lo, hi);
            int n = n0 + 2 * j;
            if (lo > bv) { bv = lo; bi = n; }
            if (hi > bv) { bv = hi; bi = n + 1; }
        }
        sval[(m0 + i) * 17 + tn] = bv;
        sidx[(m0 + i) * 17 + tn] = bi;
    }
    __syncthreads();
    if (tid < 128) {
        float bv = sval[tid * 17]; int bi = sidx[tid * 17];
        #pragma unroll
        for (int t = 1; t < 16; t++) {
            float v = sval[tid * 17 + t];
            if (v > bv) { bv = v; bi = sidx[tid * 17 + t]; }
        }
        g_amax[bk * LL + tid] = bi;
    }
}

// ---------------------------------------------------------------
// K3 v4: MLP bf16 hi/lo 3-product mma.sync.
// CTA 128x128 tile (R4 ratio), k=32/stage -> 32KB stage, 3-stage
// ring = 104.5KB smem -> 2 CTAs/SM. 144 stages (6 nt x 24 kt).
// 8 warps (2M x 4N), warp tile 64x32, product-major MMA order,
// fragment regs reused across products (temps = 32 regs).
// ---------------------------------------------------------------
#define A_BYTES 16384                     // 128 lines x 128B (hi32|lo32)
#define B_BYTES 16384
#define STAGE_B (A_BYTES + B_BYTES)       // 32 KB
#define NSTAGE 3
#define NSTG 144                          // 6 nt x 24 kt
#define MLP_SMEM (NSTAGE * STAGE_B + 128 * 17 * 4)   // 98304 + 8704 = 107008

__global__ void __launch_bounds__(256, 2) k_mlp_mma(const float* __restrict__ b1,
                                                    const float* __restrict__ w2,
                                                    const float* __restrict__ b2) {
    extern __shared__ char sm[];
    uint32_t sb = smem_u32(sm);
    float* red = (float*)(sm + NSTAGE * STAGE_B);

    int tid = threadIdx.x, lane = tid & 31, w = tid >> 5;
    int wm = w & 1, wn = w >> 1;
    size_t rowbase = (size_t)blockIdx.x * 128;

    // ---- producer mapping: lr = row/n-row, half: 0=hi 64B, 1=lo 64B ----
    int lr = tid >> 1;
    uint32_t cb0 = (uint32_t)(tid & 1) * 64;
    uint32_t swz = ((uint32_t)(lr & 7)) << 4;
    uint32_t srow = (uint32_t)lr * 128;
    const char* gAbase = (const char*)(g_xb + (rowbase + (size_t)lr) * KV)
                         + (size_t)(tid & 1) * 1536;
    const char* gBbase = (const char*)g_w1b + (size_t)(tid & 1) * 1536;

    #define ISSUE(ntp, ktp, slot) do {                                            \
        uint32_t _st = sb + (uint32_t)(slot) * STAGE_B;                            \
        const char* _ga = gAbase + (ktp) * 64;                                     \
        const char* _gb = gBbase + ((size_t)((ntp) * 128 + lr)) * 3072 + (ktp) * 64;\
        uint32_t _sa = _st + srow;                                                 \
        uint32_t _sb2 = _st + A_BYTES + srow;                                      \
        _Pragma("unroll")                                                          \
        for (int _q = 0; _q < 4; _q++) {                                           \
            uint32_t _c = (cb0 + _q * 16) ^ swz;                                   \
            CP_ASYNC16(_sa + _c, _ga + _q * 16);                                   \
            CP_ASYNC16(_sb2 + _c, _gb + _q * 16);                                  \
        }                                                                          \
        CP_COMMIT();                                                               \
    } while (0)

    // ---- consumer (ldmatrix) mapping ----
    int l15 = lane & 15;
    uint32_t sx = ((uint32_t)(lane & 7)) << 4;
    uint32_t l16 = (uint32_t)(lane >> 4) * 16;
    uint32_t aoff = (uint32_t)(wm * 64 + l15) * 128;
    uint32_t boff = (uint32_t)(wn * 32 + l15) * 128;

    float rs[4][2];
    #pragma unroll
    for (int i = 0; i < 4; i++) { rs[i][0] = 0.f; rs[i][1] = 0.f; }
    float acc[4][4][4];

    ISSUE(0, 0, 0);
    ISSUE(0, 1, 1);

    int nt = 0, kt = 0;           // consumer position
    int ntp = 0, ktp = 2;         // producer position (t+2)

    for (int t = 0; t < NSTG; t++) {
        if (t < NSTG - 1) CP_WAIT1(); else CP_WAIT0();
        __syncthreads();
        if (t + 2 < NSTG) {
            ISSUE(ntp, ktp, (t + 2) % NSTAGE);
            if (++ktp == 24) { ktp = 0; ntp++; }
        }

        if (kt == 0) {
            #pragma unroll
            for (int i = 0; i < 4; i++)
                #pragma unroll
                for (int j = 0; j < 4; j++)
                    #pragma unroll
                    for (int q = 0; q < 4; q++) acc[i][j][q] = 0.f;
        }

        uint32_t stg = sb + (uint32_t)(t % NSTAGE) * STAGE_B;
        #pragma unroll
        for (int kk = 0; kk < 2; kk++) {
            uint32_t kbh = ((uint32_t)(kk * 32) + l16) ^ sx;
            uint32_t kbl = kbh ^ 64;
            uint32_t af[4][4], th0[4], th1[4], tl0[4], tl1[4];

            // A hi + B hi
            #pragma unroll
            for (int i = 0; i < 4; i++)
                LDSM4(af[i], stg + aoff + (uint32_t)(i * 2048) + kbh);
            LDSM4(th0, stg + A_BYTES + boff + kbh);
            LDSM4(th1, stg + A_BYTES + boff + 2048 + kbh);

            // P1: hi * hi
            #pragma unroll
            for (int i = 0; i < 4; i++) {
                MMA16816(acc[i][0], af[i], th0[0], th0[2]);
                MMA16816(acc[i][1], af[i], th0[1], th0[3]);
                MMA16816(acc[i][2], af[i], th1[0], th1[2]);
                MMA16816(acc[i][3], af[i], th1[1], th1[3]);
            }

            // B lo
            LDSM4(tl0, stg + A_BYTES + boff + kbl);
            LDSM4(tl1, stg + A_BYTES + boff + 2048 + kbl);

            // P2: hi * lo
            #pragma unroll
            for (int i = 0; i < 4; i++) {
                MMA16816(acc[i][0], af[i], tl0[0], tl0[2]);
                MMA16816(acc[i][1], af[i], tl0[1], tl0[3]);
                MMA16816(acc[i][2], af[i], tl1[0], tl1[2]);
                MMA16816(acc[i][3], af[i], tl1[1], tl1[3]);
            }

            // A lo (overwrite af)
            #pragma unroll
            for (int i = 0; i < 4; i++)
                LDSM4(af[i], stg + aoff + (uint32_t)(i * 2048) + kbl);

            // P3: lo * hi
            #pragma unroll
            for (int i = 0; i < 4; i++) {
                MMA16816(acc[i][0], af[i], th0[0], th0[2]);
                MMA16816(acc[i][1], af[i], th0[1], th0[3]);
                MMA16816(acc[i][2], af[i], th1[0], th1[2]);
                MMA16816(acc[i][3], af[i], th1[1], th1[3]);
            }
        }

        if (kt == 23) {
            #pragma unroll
            for (int j = 0; j < 4; j++) {
                int col = nt * 128 + wn * 32 + j * 8 + (lane & 3) * 2;
                float b1lo = __ldg(b1 + col), b1hi = __ldg(b1 + col + 1);
                float w2lo = __ldg(w2 + col), w2hi = __ldg(w2 + col + 1);
                #pragma unroll
                for (int i = 0; i < 4; i++) {
                    rs[i][0] += fmaxf(acc[i][j][0] + b1lo, 0.f) * w2lo
                              + fmaxf(acc[i][j][1] + b1hi, 0.f) * w2hi;
                    rs[i][1] += fmaxf(acc[i][j][2] + b1lo, 0.f) * w2lo
                              + fmaxf(acc[i][j][3] + b1hi, 0.f) * w2hi;
                }
            }
        }
        if (++kt == 24) { kt = 0; nt++; }
    }
    #undef ISSUE

    // cross-thread row reduction: 16 contributors per row
    __syncthreads();
    int rcol = wn * 4 + (lane & 3);
    #pragma unroll
    for (int i = 0; i < 4; i++) {
        int row = wm * 64 + i * 16 + (lane >> 2);
        red[row * 17 + rcol] = rs[i][0];
        red[(row + 8) * 17 + rcol] = rs[i][1];
    }
    __syncthreads();
    if (tid < 128) {
        float s = b2[0];
        #pragma unroll
        for (int t = 0; t < 16; t++) s += red[tid * 17 + t];
        g_f[rowbase + tid] = s;
    }
}

// ---------------------------------------------------------------
// K4: out = f(ctx_n) + f(ent_n[argmax])
// ---------------------------------------------------------------
__global__ void k_combine(float* __restrict__ out) {
    int i = blockIdx.x * 256 + threadIdx.x;
    int bk = i / LL;
    out[i] = g_f[i] + g_f[NROWS + bk * LL + g_amax[i]];
}

extern "C" void kernel_launch(void* const* d_in, const int* in_sizes, int n_in,
                              void* d_out, int out_size) {
    const float* context = (const float*)d_in[0];
    const float* w1 = (const float*)d_in[1];
    const float* b1 = (const float*)d_in[2];
    const float* w2 = (const float*)d_in[3];
    const float* b2 = (const float*)d_in[4];
    float* out = (float*)d_out;

    k_prep_w1<<<DD, 256>>>(w1);
    k_normalize<<<NBK * 2 * LL, 192>>>(context);
    k_scores<<<NBK, 256>>>();
    cudaFuncSetAttribute(k_mlp_mma, cudaFuncAttributeMaxDynamicSharedMemorySize, MLP_SMEM);
    k_mlp_mma<<<TROWS / 128, 256, MLP_SMEM>>>(b1, w2, b2);
    k_combine<<<NROWS / 256, 256>>>(out);
}

// round 7
// speedup vs baseline: 1.3208x; 1.1634x over previous
#include <cuda_runtime.h>
#include <cuda_bf16.h>
#include <cstdint>

#define BB 4
#define KK 64
#define LL 128
#define DD 768
#define NBK (BB*KK)          // 256
#define NROWS (NBK*LL)       // 32768 per side
#define TROWS (2*NROWS)      // 65536
#define KV 1536              // packed hi|lo row length (bf16)

// ---------------- scratch ----------------
__device__ float g_ctx_n[(size_t)NROWS * DD];
__device__ float g_ent_n[(size_t)NROWS * DD];
__device__ __nv_bfloat16 g_xb[(size_t)TROWS * KV];   // [row][hi 768 | lo 768]
__device__ __nv_bfloat16 g_w1b[(size_t)DD * KV];     // [n][hi 768 | lo 768]
__device__ float g_f[TROWS];
__device__ int   g_amax[NROWS];

// ---------------- helpers ----------------
__device__ __forceinline__ uint32_t smem_u32(const void* p) {
    uint32_t a;
    asm("{ .reg .u64 t; cvta.to.shared.u64 t, %1; cvt.u32.u64 %0, t; }" : "=r"(a) : "l"(p));
    return a;
}
#define CP_ASYNC16(sa, ga) \
    asm volatile("{ .reg .u64 g; cvta.to.global.u64 g, %1; cp.async.cg.shared.global [%0], [g], 16; }" \
        :: "r"(sa), "l"(ga) : "memory")
#define CP_COMMIT() asm volatile("cp.async.commit_group;" ::: "memory")
#define CP_WAIT1()  asm volatile("cp.async.wait_group 1;" ::: "memory")
#define CP_WAIT0()  asm volatile("cp.async.wait_group 0;" ::: "memory")

#define LDSM4(r0, r1, r2, r3, a) \
    asm volatile("ldmatrix.sync.aligned.m8n8.x4.shared.b16 {%0,%1,%2,%3}, [%4];" \
        : "=r"(r0), "=r"(r1), "=r"(r2), "=r"(r3) : "r"(a))

#define MMA16816(d, a, b) \
    asm volatile("mma.sync.aligned.m16n8k16.row.col.f32.bf16.bf16.f32 " \
        "{%0,%1,%2,%3},{%4,%5,%6,%7},{%8,%9},{%0,%1,%2,%3};" \
        : "+f"((d)[0]), "+f"((d)[1]), "+f"((d)[2]), "+f"((d)[3]) \
        : "r"((a)[0]), "r"((a)[1]), "r"((a)[2]), "r"((a)[3]), "r"((b)[0]), "r"((b)[1]))

// ---------- packed f32x2 (scores kernel) ----------
__device__ __forceinline__ unsigned long long pk2(float lo, float hi) {
    unsigned long long r;
    asm("mov.b64 %0, {%1,%2};" : "=l"(r) : "f"(lo), "f"(hi));
    return r;
}
__device__ __forceinline__ void upk2(unsigned long long v, float& lo, float& hi) {
    asm("mov.b64 {%0,%1}, %2;" : "=f"(lo), "=f"(hi) : "l"(v));
}
__device__ __forceinline__ void ffma2(unsigned long long& d,
                                      unsigned long long a, unsigned long long b) {
    asm("fma.rn.f32x2 %0, %1, %2, %0;" : "+l"(d) : "l"(a), "l"(b));
}

// ---------------------------------------------------------------
// K0: w1 -> transposed bf16 hi/lo
// ---------------------------------------------------------------
__global__ void __launch_bounds__(256) k_prep_w1(const float* __restrict__ w1) {
    int n = blockIdx.x;
    for (int k = threadIdx.x; k < DD; k += 256) {
        float v = w1[(size_t)k * DD + n];
        __nv_bfloat16 h = __float2bfloat16(v);
        g_w1b[(size_t)n * KV + k] = h;
        g_w1b[(size_t)n * KV + DD + k] = __float2bfloat16(v - __bfloat162float(h));
    }
}

// ---------------------------------------------------------------
// K1: normalize rows -> fp32 (scores) + packed bf16 hi|lo (MLP)
// ---------------------------------------------------------------
__global__ void __launch_bounds__(192) k_normalize(const float* __restrict__ ctxt) {
    __shared__ float red[6];
    int r = blockIdx.x;
    int tid = threadIdx.x;
    const float4* src = (const float4*)(ctxt + (size_t)r * DD);
    float4 v = src[tid];
    float ss = v.x*v.x + v.y*v.y + v.z*v.z + v.w*v.w;
    #pragma unroll
    for (int o = 16; o; o >>= 1) ss += __shfl_xor_sync(0xffffffffu, ss, o);
    if ((tid & 31) == 0) red[tid >> 5] = ss;
    __syncthreads();
    float tot = red[0] + red[1] + red[2] + red[3] + red[4] + red[5];
    float inv = 1.0f / sqrtf(tot);
    int l  = r % LL;
    int s  = (r / LL) & 1;
    int bk = r / (2 * LL);
    size_t row32 = (size_t)bk * LL + l;
    float4 o = make_float4(v.x*inv, v.y*inv, v.z*inv, v.w*inv);
    ((float4*)((s == 0 ? g_ctx_n : g_ent_n) + row32 * DD))[tid] = o;
    size_t urow = (size_t)s * NROWS + row32;
    __nv_bfloat16 h0 = __float2bfloat16(o.x), h1 = __float2bfloat16(o.y);
    __nv_bfloat16 h2 = __float2bfloat16(o.z), h3 = __float2bfloat16(o.w);
    __nv_bfloat162* ph = (__nv_bfloat162*)(g_xb + urow * KV) + tid * 2;
    __nv_bfloat162* pl = (__nv_bfloat162*)(g_xb + urow * KV + DD) + tid * 2;
    ph[0] = __nv_bfloat162(h0, h1);
    ph[1] = __nv_bfloat162(h2, h3);
    pl[0] = __nv_bfloat162(__float2bfloat16(o.x - __bfloat162float(h0)),
                           __float2bfloat16(o.y - __bfloat162float(h1)));
    pl[1] = __nv_bfloat162(__float2bfloat16(o.z - __bfloat162float(h2)),
                           __float2bfloat16(o.w - __bfloat162float(h3)));
}

// ---------------------------------------------------------------
// K2: fp32 cosine scores + argmax (exact; argmax is tie-sensitive)
// ---------------------------------------------------------------
__global__ void __launch_bounds__(256) k_scores() {
    __shared__ float As[16 * 128];
    __shared__ float Bs[16 * 128];
    __shared__ float sval[128 * 17];
    __shared__ int   sidx[128 * 17];

    int bk = blockIdx.x;
    const float* ctxp = g_ctx_n + (size_t)bk * LL * DD;
    const float* entp = g_ent_n + (size_t)bk * LL * DD;
    int tid = threadIdx.x;
    int tm = tid & 15, tn = tid >> 4;
    int m0 = tm * 8, n0 = tn * 8;

    unsigned long long c2[8][4];
    #pragma unroll
    for (int i = 0; i < 8; i++)
        #pragma unroll
        for (int j = 0; j < 4; j++) c2[i][j] = 0ULL;

    int mrow = tid & 127;
    int hf = tid >> 7;

    for (int kt = 0; kt < 48; kt++) {
        __syncthreads();
        const float4* a4 = (const float4*)(ctxp + (size_t)mrow * DD + kt * 16);
        const float4* b4 = (const float4*)(entp + (size_t)mrow * DD + kt * 16);
        #pragma unroll
        for (int u = 0; u < 2; u++) {
            int kq = hf * 2 + u;
            float4 v = a4[kq];
            int k4 = kq * 4;
            As[(k4+0)*128+mrow] = v.x; As[(k4+1)*128+mrow] = v.y;
            As[(k4+2)*128+mrow] = v.z; As[(k4+3)*128+mrow] = v.w;
            v = b4[kq];
            Bs[(k4+0)*128+mrow] = v.x; Bs[(k4+1)*128+mrow] = v.y;
            Bs[(k4+2)*128+mrow] = v.z; Bs[(k4+3)*128+mrow] = v.w;
        }
        __syncthreads();
        #pragma unroll
        for (int kk = 0; kk < 16; kk++) {
            float4 aA = *(const float4*)(As + kk*128 + m0);
            float4 aB = *(const float4*)(As + kk*128 + m0 + 4);
            float4 bA = *(const float4*)(Bs + kk*128 + n0);
            float4 bB = *(const float4*)(Bs + kk*128 + n0 + 4);
            unsigned long long ap[8], bp[4];
            ap[0]=pk2(aA.x,aA.x); ap[1]=pk2(aA.y,aA.y); ap[2]=pk2(aA.z,aA.z); ap[3]=pk2(aA.w,aA.w);
            ap[4]=pk2(aB.x,aB.x); ap[5]=pk2(aB.y,aB.y); ap[6]=pk2(aB.z,aB.z); ap[7]=pk2(aB.w,aB.w);
            bp[0]=pk2(bA.x,bA.y); bp[1]=pk2(bA.z,bA.w); bp[2]=pk2(bB.x,bB.y); bp[3]=pk2(bB.z,bB.w);
            #pragma unroll
            for (int i = 0; i < 8; i++)
                #pragma unroll
                for (int j = 0; j < 4; j++) ffma2(c2[i][j], ap[i], bp[j]);
        }
    }

    #pragma unroll
    for (int i = 0; i < 8; i++) {
        float bv = -3.4e38f; int bi = 0;
        #pragma unroll
        for (int j = 0; j < 4; j++) {
            float lo, hi; upk2(c2[i][j], lo, hi);
            int n = n0 + 2 * j;
            if (lo > bv) { bv = lo; bi = n; }
            if (hi > bv) { bv = hi; bi = n + 1; }
        }
        sval[(m0 + i) * 17 + tn] = bv;
        sidx[(m0 + i) * 17 + tn] = bi;
    }
    __syncthreads();
    if (tid < 128) {
        float bv = sval[tid * 17]; int bi = sidx[tid * 17];
        #pragma unroll
        for (int t = 1; t < 16; t++) {
            float v = sval[tid * 17 + t];
            if (v > bv) { bv = v; bi = sidx[tid * 17 + t]; }
        }
        g_amax[bk * LL + tid] = bi;
    }
}

// ---------------------------------------------------------------
// K3 v5: exact R4 pipeline shape (128x128 tile, k=64 stage, 72
// stages, 3-stage 64KB ring, 1 CTA/SM) + product-major MMA order
// (16 independent accumulators between reuses -> no RAW stalls).
// ---------------------------------------------------------------
#define TILE16K 16384
#define STAGE_B (4 * TILE16K)                  // 64 KB
#define NSTAGE 3
#define MLP_SMEM (NSTAGE * STAGE_B + 128 * 17 * 4)   // 196608 + 8704

__global__ void __launch_bounds__(256, 1) k_mlp_mma(const float* __restrict__ b1,
                                                    const float* __restrict__ w2,
                                                    const float* __restrict__ b2) {
    extern __shared__ char sm[];
    uint32_t sb = smem_u32(sm);
    float* red = (float*)(sm + NSTAGE * STAGE_B);

    int tid = threadIdx.x, lane = tid & 31, w = tid >> 5;
    int wm = w & 1, wn = w >> 1;
    size_t rowbase = (size_t)blockIdx.x * 128;

    // ---- producer mapping: thread -> (row lr, 64B half), 4x16B per tile ----
    int lr = tid >> 1;
    uint32_t lq = (uint32_t)(tid & 1) * 64;              // byte base in 128B row
    uint32_t swst = ((uint32_t)(lr & 7)) << 4;           // store-side swizzle
    uint32_t s_row = (uint32_t)lr * 128;
    const char* gA = (const char*)(g_xb + (rowbase + (size_t)lr) * KV);

    #define ISSUE(t) do {                                                        \
        int _nt = (t) / 12, _kt = (t) % 12, _sl = (t) % NSTAGE;                   \
        const char* _ga = gA + _kt * 128;                                         \
        const char* _gb = (const char*)(g_w1b + ((size_t)(_nt * 128) + lr) * KV)  \
                          + _kt * 128;                                            \
        uint32_t _st = sb + _sl * STAGE_B + s_row;                                \
        _Pragma("unroll")                                                         \
        for (int _q = 0; _q < 4; _q++) {                                          \
            uint32_t _cb = lq + _q * 16;                                          \
            uint32_t _so = _st + (_cb ^ swst);                                    \
            CP_ASYNC16(_so,                 _ga + _cb);          /* A hi */       \
            CP_ASYNC16(_so + TILE16K,       _ga + 1536 + _cb);   /* A lo */       \
            CP_ASYNC16(_so + 2 * TILE16K,   _gb + _cb);          /* B hi */       \
            CP_ASYNC16(_so + 3 * TILE16K,   _gb + 1536 + _cb);   /* B lo */       \
        }                                                                         \
        CP_COMMIT();                                                              \
    } while (0)

    // ---- consumer (ldmatrix) mapping ----
    int l15 = lane & 15;
    uint32_t sx = ((uint32_t)(lane & 7)) << 4;           // load-side swizzle
    uint32_t l16 = (uint32_t)(lane >> 4) * 16;
    uint32_t aoff  = (uint32_t)(wm * 64 + l15) * 128;
    uint32_t boff0 = (uint32_t)(wn * 32 + l15) * 128;
    uint32_t boff1 = boff0 + 16 * 128;

    float rs[4][2];
    #pragma unroll
    for (int i = 0; i < 4; i++) { rs[i][0] = 0.f; rs[i][1] = 0.f; }
    float acc[4][4][4];

    ISSUE(0);
    ISSUE(1);

    for (int t = 0; t < 72; t++) {
        int nt = t / 12, kt = t % 12, slot = t % NSTAGE;
        if (t < 71) CP_WAIT1(); else CP_WAIT0();
        __syncthreads();
        if (t + 2 < 72) ISSUE(t + 2);

        if (kt == 0) {
            #pragma unroll
            for (int i = 0; i < 4; i++)
                #pragma unroll
                for (int j = 0; j < 4; j++)
                    #pragma unroll
                    for (int q = 0; q < 4; q++) acc[i][j][q] = 0.f;
        }

        uint32_t stg = sb + slot * STAGE_B;
        #pragma unroll
        for (int kk = 0; kk < 4; kk++) {
            uint32_t kb = ((uint32_t)(kk * 32) + l16) ^ sx;
            uint32_t ah[4][4], al[4][4], th[2][4], tl[2][4];
            #pragma unroll
            for (int i = 0; i < 4; i++) {
                uint32_t ra = stg + aoff + (uint32_t)(i * 16 * 128) + kb;
                LDSM4(ah[i][0], ah[i][1], ah[i][2], ah[i][3], ra);
                LDSM4(al[i][0], al[i][1], al[i][2], al[i][3], ra + TILE16K);
            }
            LDSM4(th[0][0], th[0][1], th[0][2], th[0][3], stg + 2*TILE16K + boff0 + kb);
            LDSM4(th[1][0], th[1][1], th[1][2], th[1][3], stg + 2*TILE16K + boff1 + kb);
            LDSM4(tl[0][0], tl[0][1], tl[0][2], tl[0][3], stg + 3*TILE16K + boff0 + kb);
            LDSM4(tl[1][0], tl[1][1], tl[1][2], tl[1][3], stg + 3*TILE16K + boff1 + kb);
            uint32_t bh[4][2], bl[4][2];
            #pragma unroll
            for (int j = 0; j < 4; j++) {
                bh[j][0] = th[j >> 1][j & 1]; bh[j][1] = th[j >> 1][(j & 1) + 2];
                bl[j][0] = tl[j >> 1][j & 1]; bl[j][1] = tl[j >> 1][(j & 1) + 2];
            }
            // product-major: 16 independent accumulators between reuses
            #pragma unroll
            for (int i = 0; i < 4; i++)
                #pragma unroll
                for (int j = 0; j < 4; j++)
                    MMA16816(acc[i][j], ah[i], bh[j]);   // hi*hi
            #pragma unroll
            for (int i = 0; i < 4; i++)
                #pragma unroll
                for (int j = 0; j < 4; j++)
                    MMA16816(acc[i][j], ah[i], bl[j]);   // hi*lo
            #pragma unroll
            for (int i = 0; i < 4; i++)
                #pragma unroll
                for (int j = 0; j < 4; j++)
                    MMA16816(acc[i][j], al[i], bh[j]);   // lo*hi
        }

        if (kt == 11) {
            #pragma unroll
            for (int j = 0; j < 4; j++) {
                int col = nt * 128 + wn * 32 + j * 8 + (lane & 3) * 2;
                float b1lo = __ldg(b1 + col), b1hi = __ldg(b1 + col + 1);
                float w2lo = __ldg(w2 + col), w2hi = __ldg(w2 + col + 1);
                #pragma unroll
                for (int i = 0; i < 4; i++) {
                    rs[i][0] += fmaxf(acc[i][j][0] + b1lo, 0.f) * w2lo
                              + fmaxf(acc[i][j][1] + b1hi, 0.f) * w2hi;
                    rs[i][1] += fmaxf(acc[i][j][2] + b1lo, 0.f) * w2lo
                              + fmaxf(acc[i][j][3] + b1hi, 0.f) * w2hi;
                }
            }
        }
    }
    #undef ISSUE

    // cross-thread row reduction: 16 contributors per row
    __syncthreads();
    int rcol = wn * 4 + (lane & 3);
    #pragma unroll
    for (int i = 0; i < 4; i++) {
        int row = wm * 64 + i * 16 + (lane >> 2);
        red[row * 17 + rcol] = rs[i][0];
        red[(row + 8) * 17 + rcol] = rs[i][1];
    }
    __syncthreads();
    if (tid < 128) {
        float s = b2[0];
        #pragma unroll
        for (int t = 0; t < 16; t++) s += red[tid * 17 + t];
        g_f[rowbase + tid] = s;
    }
}

// ---------------------------------------------------------------
// K4: out = f(ctx_n) + f(ent_n[argmax])
// ---------------------------------------------------------------
__global__ void k_combine(float* __restrict__ out) {
    int i = blockIdx.x * 256 + threadIdx.x;
    int bk = i / LL;
    out[i] = g_f[i] + g_f[NROWS + bk * LL + g_amax[i]];
}

extern "C" void kernel_launch(void* const* d_in, const int* in_sizes, int n_in,
                              void* d_out, int out_size) {
    const float* context = (const float*)d_in[0];
    const float* w1 = (const float*)d_in[1];
    const float* b1 = (const float*)d_in[2];
    const float* w2 = (const float*)d_in[3];
    const float* b2 = (const float*)d_in[4];
    float* out = (float*)d_out;

    k_prep_w1<<<DD, 256>>>(w1);
    k_normalize<<<NBK * 2 * LL, 192>>>(context);
    k_scores<<<NBK, 256>>>();
    cudaFuncSetAttribute(k_mlp_mma, cudaFuncAttributeMaxDynamicSharedMemorySize, MLP_SMEM);
    k_mlp_mma<<<TROWS / 128, 256, MLP_SMEM>>>(b1, w2, b2);
    k_combine<<<NROWS / 256, 256>>>(out);
}